// round 6
// baseline (speedup 1.0000x reference)
#include <cuda_runtime.h>

#define S_LEN 2048
#define BSZ   2
#define EMB   1024
#define NH    16
#define DH    64
#define MROWS 4096
#define NHEADS 32
#define S2 ((long)S_LEN*S_LEN)

// Scratch (__device__ globals per alloc-free rule)
__device__ float g_Qp[MROWS*EMB];
__device__ float g_Kp[MROWS*EMB];
__device__ float g_Vp[MROWS*EMB];
__device__ float g_O [MROWS*EMB];
__device__ float g_m [NHEADS*S_LEN];
__device__ float g_l [NHEADS*S_LEN];

__device__ __forceinline__ unsigned f2tf(float f){
    unsigned u; asm("cvt.rna.tf32.f32 %0, %1;" : "=r"(u) : "f"(f)); return u;
}
__device__ __forceinline__ void mma8(float* c, const unsigned* a, const unsigned* b){
    asm volatile("mma.sync.aligned.m16n8k8.row.col.f32.tf32.tf32.f32 "
      "{%0,%1,%2,%3}, {%4,%5,%6,%7}, {%8,%9}, {%0,%1,%2,%3};\n"
      : "+f"(c[0]), "+f"(c[1]), "+f"(c[2]), "+f"(c[3])
      : "r"(a[0]), "r"(a[1]), "r"(a[2]), "r"(a[3]), "r"(b[0]), "r"(b[1]));
}
__device__ __forceinline__ void cpa16(void* dst, const void* src){
    unsigned d = (unsigned)__cvta_generic_to_shared(dst);
    asm volatile("cp.async.cg.shared.global [%0], [%1], 16;\n" :: "r"(d), "l"(src));
}

// ---------------------------------------------------------------------------
// TN tf32 GEMM body (RNA cvt), used by qkv_proj and out_proj. (unchanged)
// ---------------------------------------------------------------------------
template<int BM,int BN,int BK,int WM,int WN,int NWARPS>
__device__ __forceinline__
void gemm_body(const float* __restrict__ A, int lda,
               const float* __restrict__ B, int ldb,
               float* __restrict__ C, int ldc,
               const float* __restrict__ bias, float scale, int K,
               int m0, int n0)
{
    constexpr int NT  = NWARPS*32;
    constexpr int LA  = BM*BK/(NT*4);
    constexpr int LB  = BN*BK/(NT*4);
    constexpr int WGN = BN/WN;
    constexpr int MI  = WM/16, NI = WN/8;
    constexpr int LDS_ = BK + 4;

    __shared__ unsigned As[2][BM][LDS_];
    __shared__ unsigned Bs[2][BN][LDS_];

    const int tid  = threadIdx.x;
    const int lane = tid & 31, wid = tid >> 5;
    const int wm = wid / WGN, wn = wid % WGN;

    float acc[MI][NI][4] = {};
    float4 ra[LA], rb[LB];

    auto ldtiles = [&](int k0){
        #pragma unroll
        for (int i = 0; i < LA; ++i){
            int idx = tid + i*NT;
            int r = idx / (BK/4), c = (idx % (BK/4)) * 4;
            ra[i] = *(const float4*)(A + (long)(m0+r)*lda + k0 + c);
        }
        #pragma unroll
        for (int i = 0; i < LB; ++i){
            int idx = tid + i*NT;
            int r = idx / (BK/4), c = (idx % (BK/4)) * 4;
            rb[i] = *(const float4*)(B + (long)(n0+r)*ldb + k0 + c);
        }
    };
    auto sttiles = [&](int buf){
        #pragma unroll
        for (int i = 0; i < LA; ++i){
            int idx = tid + i*NT;
            int r = idx / (BK/4), c = (idx % (BK/4)) * 4;
            uint4 u = { f2tf(ra[i].x), f2tf(ra[i].y), f2tf(ra[i].z), f2tf(ra[i].w) };
            *(uint4*)&As[buf][r][c] = u;
        }
        #pragma unroll
        for (int i = 0; i < LB; ++i){
            int idx = tid + i*NT;
            int r = idx / (BK/4), c = (idx % (BK/4)) * 4;
            uint4 u = { f2tf(rb[i].x), f2tf(rb[i].y), f2tf(rb[i].z), f2tf(rb[i].w) };
            *(uint4*)&Bs[buf][r][c] = u;
        }
    };
    auto compute = [&](int buf){
        #pragma unroll
        for (int ks = 0; ks < BK/8; ++ks){
            unsigned af[MI][4], bf[NI][2];
            #pragma unroll
            for (int mi = 0; mi < MI; ++mi){
                int m = wm*WM + mi*16 + (lane>>2);
                int k = ks*8 + (lane&3);
                af[mi][0] = As[buf][m  ][k  ];
                af[mi][1] = As[buf][m+8][k  ];
                af[mi][2] = As[buf][m  ][k+4];
                af[mi][3] = As[buf][m+8][k+4];
            }
            #pragma unroll
            for (int ni = 0; ni < NI; ++ni){
                int n = wn*WN + ni*8 + (lane>>2);
                int k = ks*8 + (lane&3);
                bf[ni][0] = Bs[buf][n][k  ];
                bf[ni][1] = Bs[buf][n][k+4];
            }
            #pragma unroll
            for (int mi = 0; mi < MI; ++mi)
                #pragma unroll
                for (int ni = 0; ni < NI; ++ni)
                    mma8(acc[mi][ni], af[mi], bf[ni]);
        }
    };

    ldtiles(0); sttiles(0); __syncthreads();
    const int nk = K/BK;
    for (int t = 1; t < nk; ++t){
        ldtiles(t*BK);
        compute((t-1)&1);
        sttiles(t&1);
        __syncthreads();
    }
    compute((nk-1)&1);

    #pragma unroll
    for (int mi = 0; mi < MI; ++mi){
        #pragma unroll
        for (int ni = 0; ni < NI; ++ni){
            int m = m0 + wm*WM + mi*16 + (lane>>2);
            int n = n0 + wn*WN + ni*8 + 2*(lane&3);
            float v0 = acc[mi][ni][0], v1 = acc[mi][ni][1];
            float v2 = acc[mi][ni][2], v3 = acc[mi][ni][3];
            float b0 = bias[n], b1 = bias[n+1];
            v0 = (v0+b0)*scale; v1 = (v1+b1)*scale;
            v2 = (v2+b0)*scale; v3 = (v3+b1)*scale;
            *(float2*)(C + (long)m    *ldc + n) = make_float2(v0, v1);
            *(float2*)(C + (long)(m+8)*ldc + n) = make_float2(v2, v3);
        }
    }
}

// Merged Q/K/V projections: grid (8, 64, 3)
__global__ __launch_bounds__(256)
void qkv_proj(const float* __restrict__ q, const float* __restrict__ k, const float* __restrict__ v,
              const float* __restrict__ qw, const float* __restrict__ qb,
              const float* __restrict__ kw, const float* __restrict__ kb,
              const float* __restrict__ vw, const float* __restrict__ vb,
              float* __restrict__ qp, float* __restrict__ kp, float* __restrict__ vp)
{
    const int z = blockIdx.z;
    const float* A  = (z==0)? q  : (z==1)? k  : v;
    const float* W  = (z==0)? qw : (z==1)? kw : vw;
    const float* bi = (z==0)? qb : (z==1)? kb : vb;
    float*       C  = (z==0)? qp : (z==1)? kp : vp;
    const float scale = (z==0)? 0.125f : 1.0f;
    gemm_body<64,128,16,32,32,8>(A, EMB, W, EMB, C, EMB, bi, scale, EMB,
                                 blockIdx.y*64, blockIdx.x*128);
}

// Output projection: grid (8, 64)
__global__ __launch_bounds__(256)
void out_proj(const float* __restrict__ A, const float* __restrict__ W,
              const float* __restrict__ bi, float* __restrict__ C)
{
    gemm_body<64,128,16,32,32,8>(A, EMB, W, EMB, C, EMB, bi, 1.0f, EMB,
                                 blockIdx.y*64, blockIdx.x*128);
}

// ---------------------------------------------------------------------------
// Flash attention v3: block = (hb, q-tile 256). 8 warps, each 32 q-rows (MI=2).
// k-tiles of 32 double-buffered via cp.async. Rescale-skip. Dynamic smem:
// Q stage 256x68 (69632 B); K/V double buffers live in its first 35840 B.
// grid (32, 8) = 256 blocks; 2 blocks/SM -> all resident, one wave.
// ---------------------------------------------------------------------------
__global__ __launch_bounds__(256, 2)
void flash_attn(const float* __restrict__ qp, const float* __restrict__ kp,
                const float* __restrict__ vp, float* __restrict__ op,
                float* __restrict__ gm, float* __restrict__ gl)
{
    extern __shared__ __align__(16) unsigned FSH[];
    const int tid = threadIdx.x, lane = tid&31, w = tid>>5;
    const int hb = blockIdx.x, h = hb&15, b = hb>>4;
    const int q0 = blockIdx.y*256;
    const long base = (long)b*EMB + h*DH;
    const float* Qg = qp + base + (long)q0*(BSZ*EMB);
    const float* Kg = kp + base;
    const float* Vg = vp + base;

    // stage Q raw, build RNA tf32 A-fragments
    for (int i = tid; i < 4096; i += 256){
        int r = i>>4, c = (i&15)*4;
        cpa16(&FSH[r*68 + c], Qg + (long)r*(BSZ*EMB) + c);
    }
    asm volatile("cp.async.commit_group;\n");
    asm volatile("cp.async.wait_group 0;\n");
    __syncthreads();

    unsigned Qa[8][2][4];
    {
        const int p = lane>>2, qq = lane&3;
        #pragma unroll
        for (int ks = 0; ks < 8; ++ks)
            #pragma unroll
            for (int mi = 0; mi < 2; ++mi){
                int m = w*32 + mi*16 + p;
                int k = ks*8 + qq;
                Qa[ks][mi][0] = f2tf(__uint_as_float(FSH[ m   *68 + k  ]));
                Qa[ks][mi][1] = f2tf(__uint_as_float(FSH[(m+8)*68 + k  ]));
                Qa[ks][mi][2] = f2tf(__uint_as_float(FSH[ m   *68 + k+4]));
                Qa[ks][mi][3] = f2tf(__uint_as_float(FSH[(m+8)*68 + k+4]));
            }
    }
    __syncthreads();

    unsigned* const Kb0 = FSH;
    unsigned* const Kb1 = FSH + 2176;
    unsigned* const Vb0 = FSH + 4352;
    unsigned* const Vb1 = FSH + 6656;

    auto load_kv = [&](int kt, int sel){
        unsigned* Kb = sel ? Kb1 : Kb0;
        unsigned* Vb = sel ? Vb1 : Vb0;
        const long r0 = (long)kt*32;
        #pragma unroll
        for (int j = 0; j < 2; ++j){
            int cch = tid + j*256;            // 0..511
            int r = cch>>4, cc = (cch&15)*4;
            cpa16(&Kb[r*68 + cc], Kg + (r0+r)*(BSZ*EMB) + cc);
            cpa16(&Vb[r*72 + cc], Vg + (r0+r)*(BSZ*EMB) + cc);
        }
    };

    float m_[2][2] = {{-1e30f,-1e30f},{-1e30f,-1e30f}};
    float l_[2][2] = {};
    float o[2][8][4] = {};

    const int srcA = (lane & ~3) | ((lane&3)>>1);
    const int srcB = srcA + 2;
    const bool osel = (lane & 1);

    load_kv(0, 0);
    asm volatile("cp.async.commit_group;\n");

    for (int t = 0; t < 64; ++t){
        if (t < 63){
            load_kv(t+1, (t+1)&1);
            asm volatile("cp.async.commit_group;\n");
            asm volatile("cp.async.wait_group 1;\n");
        } else {
            asm volatile("cp.async.wait_group 0;\n");
        }
        __syncthreads();

        unsigned* Kb = (t&1) ? Kb1 : Kb0;
        unsigned* Vb = (t&1) ? Vb1 : Vb0;

        // S = Q K^T
        float c_[2][4][4] = {};
        #pragma unroll
        for (int ks = 0; ks < 8; ++ks){
            unsigned bf[4][2];
            #pragma unroll
            for (int ni = 0; ni < 4; ++ni){
                int n = ni*8 + (lane>>2);
                int k = ks*8 + (lane&3);
                bf[ni][0] = Kb[n*68 + k];
                bf[ni][1] = Kb[n*68 + k+4];
            }
            #pragma unroll
            for (int mi = 0; mi < 2; ++mi)
                #pragma unroll
                for (int ni = 0; ni < 4; ++ni)
                    mma8(c_[mi][ni], Qa[ks][mi], bf[ni]);
        }

        // online softmax with rescale-skip
        #pragma unroll
        for (int mi = 0; mi < 2; ++mi){
            float mx0 = -1e30f, mx1 = -1e30f;
            #pragma unroll
            for (int ni = 0; ni < 4; ++ni){
                mx0 = fmaxf(mx0, fmaxf(c_[mi][ni][0], c_[mi][ni][1]));
                mx1 = fmaxf(mx1, fmaxf(c_[mi][ni][2], c_[mi][ni][3]));
            }
            mx0 = fmaxf(mx0, __shfl_xor_sync(0xffffffffu, mx0, 1));
            mx0 = fmaxf(mx0, __shfl_xor_sync(0xffffffffu, mx0, 2));
            mx1 = fmaxf(mx1, __shfl_xor_sync(0xffffffffu, mx1, 1));
            mx1 = fmaxf(mx1, __shfl_xor_sync(0xffffffffu, mx1, 2));
            float mn0 = fmaxf(m_[mi][0], mx0), mn1 = fmaxf(m_[mi][1], mx1);
            if (!__all_sync(0xffffffffu, (mn0 == m_[mi][0]) & (mn1 == m_[mi][1]))){
                float f0 = __expf(m_[mi][0] - mn0), f1 = __expf(m_[mi][1] - mn1);
                l_[mi][0] *= f0; l_[mi][1] *= f1;
                #pragma unroll
                for (int ni = 0; ni < 8; ++ni){
                    o[mi][ni][0]*=f0; o[mi][ni][1]*=f0;
                    o[mi][ni][2]*=f1; o[mi][ni][3]*=f1;
                }
                m_[mi][0] = mn0; m_[mi][1] = mn1;
            }
            float s0 = 0.f, s1 = 0.f;
            #pragma unroll
            for (int ni = 0; ni < 4; ++ni){
                c_[mi][ni][0] = __expf(c_[mi][ni][0]-m_[mi][0]);
                c_[mi][ni][1] = __expf(c_[mi][ni][1]-m_[mi][0]);
                c_[mi][ni][2] = __expf(c_[mi][ni][2]-m_[mi][1]);
                c_[mi][ni][3] = __expf(c_[mi][ni][3]-m_[mi][1]);
                s0 += c_[mi][ni][0]+c_[mi][ni][1];
                s1 += c_[mi][ni][2]+c_[mi][ni][3];
            }
            s0 += __shfl_xor_sync(0xffffffffu, s0, 1);
            s0 += __shfl_xor_sync(0xffffffffu, s0, 2);
            s1 += __shfl_xor_sync(0xffffffffu, s1, 1);
            s1 += __shfl_xor_sync(0xffffffffu, s1, 2);
            l_[mi][0] += s0; l_[mi][1] += s1;
        }

        // P @ V
        #pragma unroll
        for (int ks2 = 0; ks2 < 4; ++ks2){
            unsigned a[2][4];
            #pragma unroll
            for (int mi = 0; mi < 2; ++mi){
                float v00 = __shfl_sync(0xffffffffu, c_[mi][ks2][0], srcA);
                float v01 = __shfl_sync(0xffffffffu, c_[mi][ks2][1], srcA);
                float v10 = __shfl_sync(0xffffffffu, c_[mi][ks2][2], srcA);
                float v11 = __shfl_sync(0xffffffffu, c_[mi][ks2][3], srcA);
                float v40 = __shfl_sync(0xffffffffu, c_[mi][ks2][0], srcB);
                float v41 = __shfl_sync(0xffffffffu, c_[mi][ks2][1], srcB);
                float v50 = __shfl_sync(0xffffffffu, c_[mi][ks2][2], srcB);
                float v51 = __shfl_sync(0xffffffffu, c_[mi][ks2][3], srcB);
                a[mi][0] = f2tf(osel ? v01 : v00);
                a[mi][1] = f2tf(osel ? v11 : v10);
                a[mi][2] = f2tf(osel ? v41 : v40);
                a[mi][3] = f2tf(osel ? v51 : v50);
            }
            #pragma unroll
            for (int ni = 0; ni < 8; ++ni){
                int kk = ks2*8 + (lane&3);
                int n  = ni*8 + (lane>>2);
                unsigned bf[2] = { Vb[kk*72 + n], Vb[(kk+4)*72 + n] };
                mma8(o[0][ni], a[0], bf);
                mma8(o[1][ni], a[1], bf);
            }
        }
        __syncthreads();
    }

    float* Og = op + base + (long)q0*(BSZ*EMB);
    #pragma unroll
    for (int mi = 0; mi < 2; ++mi){
        float inv0 = 1.f/l_[mi][0], inv1 = 1.f/l_[mi][1];
        int m = w*32 + mi*16 + (lane>>2);
        #pragma unroll
        for (int ni = 0; ni < 8; ++ni){
            int d = ni*8 + 2*(lane&3);
            *(float2*)(Og + (long)m    *(BSZ*EMB) + d) = make_float2(o[mi][ni][0]*inv0, o[mi][ni][1]*inv0);
            *(float2*)(Og + (long)(m+8)*(BSZ*EMB) + d) = make_float2(o[mi][ni][2]*inv1, o[mi][ni][3]*inv1);
        }
        if ((lane & 3) == 0){
            gm[(long)hb*S_LEN + q0 + m]     = m_[mi][0];
            gm[(long)hb*S_LEN + q0 + m + 8] = m_[mi][1];
            gl[(long)hb*S_LEN + q0 + m]     = l_[mi][0];
            gl[(long)hb*S_LEN + q0 + m + 8] = l_[mi][1];
        }
    }
}

// ---------------------------------------------------------------------------
// attn_avg v4: 256-thread blocks (2 blocks/SM -> occ 50%).
// block = (k-tile 64, q-tile 128, b); 8 warps, each 16 q-rows x 64 k-cols.
// Double-buffered head pipeline. Dynamic smem: 2 x (128*68 + 64*68) x 4 B.
// ---------------------------------------------------------------------------
__global__ __launch_bounds__(256)
void avg_attn(const float* __restrict__ qp, const float* __restrict__ kp,
              const float* __restrict__ gm, const float* __restrict__ gl,
              float* __restrict__ avg)
{
    extern __shared__ __align__(16) unsigned ASH[];
    constexpr int BUF = 128*68 + 64*68;   // 13056 words per buffer
    const int tid = threadIdx.x, lane = tid&31, wid = tid>>5;
    const int k0 = blockIdx.x*64, q0 = blockIdx.y*128, b = blockIdx.z;
    const int rloc = wid*16 + (lane>>2);

    auto stage = [&](int h, int sel){
        unsigned* Qs = ASH + sel*BUF;
        unsigned* Ks = Qs + 128*68;
        const long base = (long)b*EMB + h*DH;
        #pragma unroll
        for (int j = 0; j < 8; ++j){          // Q: 128 rows x 16 chunks
            int idx = tid + j*256;
            int r = idx>>4, c = (idx&15)*4;
            cpa16(&Qs[r*68 + c], qp + base + (long)(q0+r)*(BSZ*EMB) + c);
        }
        #pragma unroll
        for (int j = 0; j < 4; ++j){          // K: 64 rows x 16 chunks
            int idx = tid + j*256;
            int r = idx>>4, c = (idx&15)*4;
            cpa16(&Ks[r*68 + c], kp + base + (long)(k0+r)*(BSZ*EMB) + c);
        }
        asm volatile("cp.async.commit_group;\n");
    };

    float acc[8][4] = {};

    stage(0, 0);
    for (int h = 0; h < NH; ++h){
        if (h < NH-1){
            stage(h+1, (h+1)&1);
            asm volatile("cp.async.wait_group 1;\n");
        } else {
            asm volatile("cp.async.wait_group 0;\n");
        }
        __syncthreads();

        unsigned* Qs = ASH + (h&1)*BUF;
        unsigned* Ks = Qs + 128*68;

        float c_[8][4] = {};
        #pragma unroll
        for (int ks = 0; ks < 8; ++ks){
            unsigned a[4];
            int k = ks*8 + (lane&3);
            a[0] = f2tf(__uint_as_float(Qs[ rloc   *68 + k  ]));
            a[1] = f2tf(__uint_as_float(Qs[(rloc+8)*68 + k  ]));
            a[2] = f2tf(__uint_as_float(Qs[ rloc   *68 + k+4]));
            a[3] = f2tf(__uint_as_float(Qs[(rloc+8)*68 + k+4]));
            #pragma unroll
            for (int ni = 0; ni < 8; ++ni){
                int n = ni*8 + (lane>>2);
                unsigned bf[2] = { Ks[n*68 + k], Ks[n*68 + k+4] };
                mma8(c_[ni], a, bf);
            }
        }

        const int hb = b*NH + h;
        float mm0 = gm[(long)hb*S_LEN + q0 + rloc];
        float mm1 = gm[(long)hb*S_LEN + q0 + rloc + 8];
        float il0 = 1.f / gl[(long)hb*S_LEN + q0 + rloc];
        float il1 = 1.f / gl[(long)hb*S_LEN + q0 + rloc + 8];
        #pragma unroll
        for (int ni = 0; ni < 8; ++ni){
            acc[ni][0] += __expf(c_[ni][0]-mm0)*il0;
            acc[ni][1] += __expf(c_[ni][1]-mm0)*il0;
            acc[ni][2] += __expf(c_[ni][2]-mm1)*il1;
            acc[ni][3] += __expf(c_[ni][3]-mm1)*il1;
        }
        __syncthreads();
    }

    float* out = avg + (long)b*S2;
    const float s = 1.0f/NH;
    #pragma unroll
    for (int ni = 0; ni < 8; ++ni){
        int kc = k0 + ni*8 + 2*(lane&3);
        *(float2*)(out + (long)(q0+rloc)  *S_LEN + kc) = make_float2(acc[ni][0]*s, acc[ni][1]*s);
        *(float2*)(out + (long)(q0+rloc+8)*S_LEN + kc) = make_float2(acc[ni][2]*s, acc[ni][3]*s);
    }
}

// ---------------------------------------------------------------------------
extern "C" void kernel_launch(void* const* d_in, const int* in_sizes, int n_in,
                              void* d_out, int out_size)
{
    const float* query = (const float*)d_in[0];
    const float* key   = (const float*)d_in[1];
    const float* value = (const float*)d_in[2];
    const float* q_w = (const float*)d_in[3];
    const float* q_b = (const float*)d_in[4];
    const float* k_w = (const float*)d_in[5];
    const float* k_b = (const float*)d_in[6];
    const float* v_w = (const float*)d_in[7];
    const float* v_b = (const float*)d_in[8];
    const float* out_w = (const float*)d_in[9];
    const float* out_b = (const float*)d_in[10];

    float *qp, *kp, *vp, *op, *gm, *gl;
    cudaGetSymbolAddress((void**)&qp, g_Qp);
    cudaGetSymbolAddress((void**)&kp, g_Kp);
    cudaGetSymbolAddress((void**)&vp, g_Vp);
    cudaGetSymbolAddress((void**)&op, g_O);
    cudaGetSymbolAddress((void**)&gm, g_m);
    cudaGetSymbolAddress((void**)&gl, g_l);

    float* Z = (float*)d_out;                          // [S,B,E]
    float* attn_avg = (float*)d_out + (long)MROWS*EMB; // [B,S,S]

    // 1) Q/K/V projections merged
    dim3 gqkv(EMB/128, MROWS/64, 3);
    qkv_proj<<<gqkv, 256>>>(query, key, value, q_w, q_b, k_w, k_b, v_w, v_b, qp, kp, vp);

    // 2) Flash attention: grid (32 heads, 8 q-tiles), dynamic smem 68KB
    cudaFuncSetAttribute(flash_attn, cudaFuncAttributeMaxDynamicSharedMemorySize, 69632);
    dim3 gfa(NHEADS, S_LEN/256, 1);
    flash_attn<<<gfa, 256, 69632>>>(qp, kp, vp, op, gm, gl);

    // 3) Output projection
    dim3 gop(EMB/128, MROWS/64, 1);
    out_proj<<<gop, 256>>>(op, out_w, out_b, Z);

    // 4) attn_avg, 256-thread blocks, double-buffered heads (dyn smem 102KB)
    cudaFuncSetAttribute(avg_attn, cudaFuncAttributeMaxDynamicSharedMemorySize, 104448);
    dim3 gav(S_LEN/64, S_LEN/128, BSZ);
    avg_attn<<<gav, 256, 104448>>>(qp, kp, gm, gl, attn_avg);
}

// round 7
// speedup vs baseline: 1.1803x; 1.1803x over previous
#include <cuda_runtime.h>

#define S_LEN 2048
#define BSZ   2
#define EMB   1024
#define NH    16
#define DH    64
#define MROWS 4096
#define NHEADS 32
#define S2 ((long)S_LEN*S_LEN)

// Scratch (__device__ globals per alloc-free rule)
__device__ float g_Qp[MROWS*EMB];
__device__ float g_Kp[MROWS*EMB];
__device__ float g_Vp[MROWS*EMB];
__device__ float g_O [MROWS*EMB];
__device__ float g_m [NHEADS*S_LEN];
__device__ float g_l [NHEADS*S_LEN];

__device__ __forceinline__ unsigned f2tf(float f){
    unsigned u; asm("cvt.rna.tf32.f32 %0, %1;" : "=r"(u) : "f"(f)); return u;
}
__device__ __forceinline__ void mma8(float* c, const unsigned* a, const unsigned* b){
    asm volatile("mma.sync.aligned.m16n8k8.row.col.f32.tf32.tf32.f32 "
      "{%0,%1,%2,%3}, {%4,%5,%6,%7}, {%8,%9}, {%0,%1,%2,%3};\n"
      : "+f"(c[0]), "+f"(c[1]), "+f"(c[2]), "+f"(c[3])
      : "r"(a[0]), "r"(a[1]), "r"(a[2]), "r"(a[3]), "r"(b[0]), "r"(b[1]));
}
__device__ __forceinline__ void cpa16(void* dst, const void* src){
    unsigned d = (unsigned)__cvta_generic_to_shared(dst);
    asm volatile("cp.async.cg.shared.global [%0], [%1], 16;\n" :: "r"(d), "l"(src));
}

// ---------------------------------------------------------------------------
// TN tf32 GEMM body (RNA cvt), used by qkv_proj and out_proj.
// ---------------------------------------------------------------------------
template<int BM,int BN,int BK,int WM,int WN,int NWARPS>
__device__ __forceinline__
void gemm_body(const float* __restrict__ A, int lda,
               const float* __restrict__ B, int ldb,
               float* __restrict__ C, int ldc,
               const float* __restrict__ bias, float scale, int K,
               int m0, int n0)
{
    constexpr int NT  = NWARPS*32;
    constexpr int LA  = BM*BK/(NT*4);
    constexpr int LB  = BN*BK/(NT*4);
    constexpr int WGN = BN/WN;
    constexpr int MI  = WM/16, NI = WN/8;
    constexpr int LDS_ = BK + 4;

    __shared__ unsigned As[2][BM][LDS_];
    __shared__ unsigned Bs[2][BN][LDS_];

    const int tid  = threadIdx.x;
    const int lane = tid & 31, wid = tid >> 5;
    const int wm = wid / WGN, wn = wid % WGN;

    float acc[MI][NI][4] = {};
    float4 ra[LA], rb[LB];

    auto ldtiles = [&](int k0){
        #pragma unroll
        for (int i = 0; i < LA; ++i){
            int idx = tid + i*NT;
            int r = idx / (BK/4), c = (idx % (BK/4)) * 4;
            ra[i] = *(const float4*)(A + (long)(m0+r)*lda + k0 + c);
        }
        #pragma unroll
        for (int i = 0; i < LB; ++i){
            int idx = tid + i*NT;
            int r = idx / (BK/4), c = (idx % (BK/4)) * 4;
            rb[i] = *(const float4*)(B + (long)(n0+r)*ldb + k0 + c);
        }
    };
    auto sttiles = [&](int buf){
        #pragma unroll
        for (int i = 0; i < LA; ++i){
            int idx = tid + i*NT;
            int r = idx / (BK/4), c = (idx % (BK/4)) * 4;
            uint4 u = { f2tf(ra[i].x), f2tf(ra[i].y), f2tf(ra[i].z), f2tf(ra[i].w) };
            *(uint4*)&As[buf][r][c] = u;
        }
        #pragma unroll
        for (int i = 0; i < LB; ++i){
            int idx = tid + i*NT;
            int r = idx / (BK/4), c = (idx % (BK/4)) * 4;
            uint4 u = { f2tf(rb[i].x), f2tf(rb[i].y), f2tf(rb[i].z), f2tf(rb[i].w) };
            *(uint4*)&Bs[buf][r][c] = u;
        }
    };
    auto compute = [&](int buf){
        #pragma unroll
        for (int ks = 0; ks < BK/8; ++ks){
            unsigned af[MI][4], bf[NI][2];
            #pragma unroll
            for (int mi = 0; mi < MI; ++mi){
                int m = wm*WM + mi*16 + (lane>>2);
                int k = ks*8 + (lane&3);
                af[mi][0] = As[buf][m  ][k  ];
                af[mi][1] = As[buf][m+8][k  ];
                af[mi][2] = As[buf][m  ][k+4];
                af[mi][3] = As[buf][m+8][k+4];
            }
            #pragma unroll
            for (int ni = 0; ni < NI; ++ni){
                int n = wn*WN + ni*8 + (lane>>2);
                int k = ks*8 + (lane&3);
                bf[ni][0] = Bs[buf][n][k  ];
                bf[ni][1] = Bs[buf][n][k+4];
            }
            #pragma unroll
            for (int mi = 0; mi < MI; ++mi)
                #pragma unroll
                for (int ni = 0; ni < NI; ++ni)
                    mma8(acc[mi][ni], af[mi], bf[ni]);
        }
    };

    ldtiles(0); sttiles(0); __syncthreads();
    const int nk = K/BK;
    for (int t = 1; t < nk; ++t){
        ldtiles(t*BK);
        compute((t-1)&1);
        sttiles(t&1);
        __syncthreads();
    }
    compute((nk-1)&1);

    #pragma unroll
    for (int mi = 0; mi < MI; ++mi){
        #pragma unroll
        for (int ni = 0; ni < NI; ++ni){
            int m = m0 + wm*WM + mi*16 + (lane>>2);
            int n = n0 + wn*WN + ni*8 + 2*(lane&3);
            float v0 = acc[mi][ni][0], v1 = acc[mi][ni][1];
            float v2 = acc[mi][ni][2], v3 = acc[mi][ni][3];
            float b0 = bias[n], b1 = bias[n+1];
            v0 = (v0+b0)*scale; v1 = (v1+b1)*scale;
            v2 = (v2+b0)*scale; v3 = (v3+b1)*scale;
            *(float2*)(C + (long)m    *ldc + n) = make_float2(v0, v1);
            *(float2*)(C + (long)(m+8)*ldc + n) = make_float2(v2, v3);
        }
    }
}

// Merged Q/K/V projections: grid (8, 64, 3)
__global__ __launch_bounds__(256)
void qkv_proj(const float* __restrict__ q, const float* __restrict__ k, const float* __restrict__ v,
              const float* __restrict__ qw, const float* __restrict__ qb,
              const float* __restrict__ kw, const float* __restrict__ kb,
              const float* __restrict__ vw, const float* __restrict__ vb,
              float* __restrict__ qp, float* __restrict__ kp, float* __restrict__ vp)
{
    const int z = blockIdx.z;
    const float* A  = (z==0)? q  : (z==1)? k  : v;
    const float* W  = (z==0)? qw : (z==1)? kw : vw;
    const float* bi = (z==0)? qb : (z==1)? kb : vb;
    float*       C  = (z==0)? qp : (z==1)? kp : vp;
    const float scale = (z==0)? 0.125f : 1.0f;
    gemm_body<64,128,16,32,32,8>(A, EMB, W, EMB, C, EMB, bi, scale, EMB,
                                 blockIdx.y*64, blockIdx.x*128);
}

// Output projection: grid (8, 64)
__global__ __launch_bounds__(256)
void out_proj(const float* __restrict__ A, const float* __restrict__ W,
              const float* __restrict__ bi, float* __restrict__ C)
{
    gemm_body<64,128,16,32,32,8>(A, EMB, W, EMB, C, EMB, bi, 1.0f, EMB,
                                 blockIdx.y*64, blockIdx.x*128);
}

// ---------------------------------------------------------------------------
// Flash attention (round-5 proven version): block = (hb, q-tile 128).
// 4 warps (MI=2). k-tiles of 32 double-buffered via cp.async. Rescale-skip.
// ---------------------------------------------------------------------------
__global__ __launch_bounds__(128)
void flash_attn(const float* __restrict__ qp, const float* __restrict__ kp,
                const float* __restrict__ vp, float* __restrict__ op,
                float* __restrict__ gm, float* __restrict__ gl)
{
    __shared__ __align__(16) unsigned SU[8960];
    const int tid = threadIdx.x, lane = tid&31, w = tid>>5;
    const int hb = blockIdx.x, h = hb&15, b = hb>>4;
    const int q0 = blockIdx.y*128;
    const long base = (long)b*EMB + h*DH;
    const float* Qg = qp + base + (long)q0*(BSZ*EMB);
    const float* Kg = kp + base;
    const float* Vg = vp + base;

    // stage Q raw, build RNA tf32 A-fragments
    for (int i = tid; i < 2048; i += 128){
        int r = i>>4, c = (i&15)*4;
        cpa16(&SU[r*68 + c], Qg + (long)r*(BSZ*EMB) + c);
    }
    asm volatile("cp.async.commit_group;\n");
    asm volatile("cp.async.wait_group 0;\n");
    __syncthreads();

    unsigned Qa[8][2][4];
    {
        const int p = lane>>2, qq = lane&3;
        #pragma unroll
        for (int ks = 0; ks < 8; ++ks)
            #pragma unroll
            for (int mi = 0; mi < 2; ++mi){
                int m = w*32 + mi*16 + p;
                int k = ks*8 + qq;
                Qa[ks][mi][0] = f2tf(__uint_as_float(SU[ m   *68 + k  ]));
                Qa[ks][mi][1] = f2tf(__uint_as_float(SU[(m+8)*68 + k  ]));
                Qa[ks][mi][2] = f2tf(__uint_as_float(SU[ m   *68 + k+4]));
                Qa[ks][mi][3] = f2tf(__uint_as_float(SU[(m+8)*68 + k+4]));
            }
    }
    __syncthreads();

    unsigned* const Kb0 = SU;
    unsigned* const Kb1 = SU + 2176;
    unsigned* const Vb0 = SU + 4352;
    unsigned* const Vb1 = SU + 6656;

    auto load_kv = [&](int kt, int sel){
        unsigned* Kb = sel ? Kb1 : Kb0;
        unsigned* Vb = sel ? Vb1 : Vb0;
        const long r0 = (long)kt*32;
        #pragma unroll
        for (int j = 0; j < 4; ++j){
            int cch = tid + j*128;
            int r = cch>>4, cc = (cch&15)*4;
            cpa16(&Kb[r*68 + cc], Kg + (r0+r)*(BSZ*EMB) + cc);
            cpa16(&Vb[r*72 + cc], Vg + (r0+r)*(BSZ*EMB) + cc);
        }
    };

    float m_[2][2] = {{-1e30f,-1e30f},{-1e30f,-1e30f}};
    float l_[2][2] = {};
    float o[2][8][4] = {};

    const int srcA = (lane & ~3) | ((lane&3)>>1);
    const int srcB = srcA + 2;
    const bool osel = (lane & 1);

    load_kv(0, 0);
    asm volatile("cp.async.commit_group;\n");

    for (int t = 0; t < 64; ++t){
        if (t < 63){
            load_kv(t+1, (t+1)&1);
            asm volatile("cp.async.commit_group;\n");
            asm volatile("cp.async.wait_group 1;\n");
        } else {
            asm volatile("cp.async.wait_group 0;\n");
        }
        __syncthreads();

        unsigned* Kb = (t&1) ? Kb1 : Kb0;
        unsigned* Vb = (t&1) ? Vb1 : Vb0;

        // S = Q K^T
        float c_[2][4][4] = {};
        #pragma unroll
        for (int ks = 0; ks < 8; ++ks){
            unsigned bf[4][2];
            #pragma unroll
            for (int ni = 0; ni < 4; ++ni){
                int n = ni*8 + (lane>>2);
                int k = ks*8 + (lane&3);
                bf[ni][0] = Kb[n*68 + k];
                bf[ni][1] = Kb[n*68 + k+4];
            }
            #pragma unroll
            for (int mi = 0; mi < 2; ++mi)
                #pragma unroll
                for (int ni = 0; ni < 4; ++ni)
                    mma8(c_[mi][ni], Qa[ks][mi], bf[ni]);
        }

        // online softmax with rescale-skip
        #pragma unroll
        for (int mi = 0; mi < 2; ++mi){
            float mx0 = -1e30f, mx1 = -1e30f;
            #pragma unroll
            for (int ni = 0; ni < 4; ++ni){
                mx0 = fmaxf(mx0, fmaxf(c_[mi][ni][0], c_[mi][ni][1]));
                mx1 = fmaxf(mx1, fmaxf(c_[mi][ni][2], c_[mi][ni][3]));
            }
            mx0 = fmaxf(mx0, __shfl_xor_sync(0xffffffffu, mx0, 1));
            mx0 = fmaxf(mx0, __shfl_xor_sync(0xffffffffu, mx0, 2));
            mx1 = fmaxf(mx1, __shfl_xor_sync(0xffffffffu, mx1, 1));
            mx1 = fmaxf(mx1, __shfl_xor_sync(0xffffffffu, mx1, 2));
            float mn0 = fmaxf(m_[mi][0], mx0), mn1 = fmaxf(m_[mi][1], mx1);
            if (!__all_sync(0xffffffffu, (mn0 == m_[mi][0]) & (mn1 == m_[mi][1]))){
                float f0 = __expf(m_[mi][0] - mn0), f1 = __expf(m_[mi][1] - mn1);
                l_[mi][0] *= f0; l_[mi][1] *= f1;
                #pragma unroll
                for (int ni = 0; ni < 8; ++ni){
                    o[mi][ni][0]*=f0; o[mi][ni][1]*=f0;
                    o[mi][ni][2]*=f1; o[mi][ni][3]*=f1;
                }
                m_[mi][0] = mn0; m_[mi][1] = mn1;
            }
            float s0 = 0.f, s1 = 0.f;
            #pragma unroll
            for (int ni = 0; ni < 4; ++ni){
                c_[mi][ni][0] = __expf(c_[mi][ni][0]-m_[mi][0]);
                c_[mi][ni][1] = __expf(c_[mi][ni][1]-m_[mi][0]);
                c_[mi][ni][2] = __expf(c_[mi][ni][2]-m_[mi][1]);
                c_[mi][ni][3] = __expf(c_[mi][ni][3]-m_[mi][1]);
                s0 += c_[mi][ni][0]+c_[mi][ni][1];
                s1 += c_[mi][ni][2]+c_[mi][ni][3];
            }
            s0 += __shfl_xor_sync(0xffffffffu, s0, 1);
            s0 += __shfl_xor_sync(0xffffffffu, s0, 2);
            s1 += __shfl_xor_sync(0xffffffffu, s1, 1);
            s1 += __shfl_xor_sync(0xffffffffu, s1, 2);
            l_[mi][0] += s0; l_[mi][1] += s1;
        }

        // P @ V
        #pragma unroll
        for (int ks2 = 0; ks2 < 4; ++ks2){
            unsigned a[2][4];
            #pragma unroll
            for (int mi = 0; mi < 2; ++mi){
                float v00 = __shfl_sync(0xffffffffu, c_[mi][ks2][0], srcA);
                float v01 = __shfl_sync(0xffffffffu, c_[mi][ks2][1], srcA);
                float v10 = __shfl_sync(0xffffffffu, c_[mi][ks2][2], srcA);
                float v11 = __shfl_sync(0xffffffffu, c_[mi][ks2][3], srcA);
                float v40 = __shfl_sync(0xffffffffu, c_[mi][ks2][0], srcB);
                float v41 = __shfl_sync(0xffffffffu, c_[mi][ks2][1], srcB);
                float v50 = __shfl_sync(0xffffffffu, c_[mi][ks2][2], srcB);
                float v51 = __shfl_sync(0xffffffffu, c_[mi][ks2][3], srcB);
                a[mi][0] = f2tf(osel ? v01 : v00);
                a[mi][1] = f2tf(osel ? v11 : v10);
                a[mi][2] = f2tf(osel ? v41 : v40);
                a[mi][3] = f2tf(osel ? v51 : v50);
            }
            #pragma unroll
            for (int ni = 0; ni < 8; ++ni){
                int kk = ks2*8 + (lane&3);
                int n  = ni*8 + (lane>>2);
                unsigned bf[2] = { Vb[kk*72 + n], Vb[(kk+4)*72 + n] };
                mma8(o[0][ni], a[0], bf);
                mma8(o[1][ni], a[1], bf);
            }
        }
        __syncthreads();
    }

    float* Og = op + base + (long)q0*(BSZ*EMB);
    #pragma unroll
    for (int mi = 0; mi < 2; ++mi){
        float inv0 = 1.f/l_[mi][0], inv1 = 1.f/l_[mi][1];
        int m = w*32 + mi*16 + (lane>>2);
        #pragma unroll
        for (int ni = 0; ni < 8; ++ni){
            int d = ni*8 + 2*(lane&3);
            *(float2*)(Og + (long)m    *(BSZ*EMB) + d) = make_float2(o[mi][ni][0]*inv0, o[mi][ni][1]*inv0);
            *(float2*)(Og + (long)(m+8)*(BSZ*EMB) + d) = make_float2(o[mi][ni][2]*inv1, o[mi][ni][3]*inv1);
        }
        if ((lane & 3) == 0){
            gm[(long)hb*S_LEN + q0 + m]     = m_[mi][0];
            gm[(long)hb*S_LEN + q0 + m + 8] = m_[mi][1];
            gl[(long)hb*S_LEN + q0 + m]     = l_[mi][0];
            gl[(long)hb*S_LEN + q0 + m + 8] = l_[mi][1];
        }
    }
}

// ---------------------------------------------------------------------------
// attn_avg v4 (round-6 proven): 256-thread blocks, k-tile 64, q-tile 128,
// double-buffered head pipeline. Dynamic smem 104448 B.
// ---------------------------------------------------------------------------
__global__ __launch_bounds__(256)
void avg_attn(const float* __restrict__ qp, const float* __restrict__ kp,
              const float* __restrict__ gm, const float* __restrict__ gl,
              float* __restrict__ avg)
{
    extern __shared__ __align__(16) unsigned ASH[];
    constexpr int BUF = 128*68 + 64*68;
    const int tid = threadIdx.x, lane = tid&31, wid = tid>>5;
    const int k0 = blockIdx.x*64, q0 = blockIdx.y*128, b = blockIdx.z;
    const int rloc = wid*16 + (lane>>2);

    auto stage = [&](int h, int sel){
        unsigned* Qs = ASH + sel*BUF;
        unsigned* Ks = Qs + 128*68;
        const long base = (long)b*EMB + h*DH;
        #pragma unroll
        for (int j = 0; j < 8; ++j){
            int idx = tid + j*256;
            int r = idx>>4, c = (idx&15)*4;
            cpa16(&Qs[r*68 + c], qp + base + (long)(q0+r)*(BSZ*EMB) + c);
        }
        #pragma unroll
        for (int j = 0; j < 4; ++j){
            int idx = tid + j*256;
            int r = idx>>4, c = (idx&15)*4;
            cpa16(&Ks[r*68 + c], kp + base + (long)(k0+r)*(BSZ*EMB) + c);
        }
        asm volatile("cp.async.commit_group;\n");
    };

    float acc[8][4] = {};

    stage(0, 0);
    for (int h = 0; h < NH; ++h){
        if (h < NH-1){
            stage(h+1, (h+1)&1);
            asm volatile("cp.async.wait_group 1;\n");
        } else {
            asm volatile("cp.async.wait_group 0;\n");
        }
        __syncthreads();

        unsigned* Qs = ASH + (h&1)*BUF;
        unsigned* Ks = Qs + 128*68;

        float c_[8][4] = {};
        #pragma unroll
        for (int ks = 0; ks < 8; ++ks){
            unsigned a[4];
            int k = ks*8 + (lane&3);
            a[0] = f2tf(__uint_as_float(Qs[ rloc   *68 + k  ]));
            a[1] = f2tf(__uint_as_float(Qs[(rloc+8)*68 + k  ]));
            a[2] = f2tf(__uint_as_float(Qs[ rloc   *68 + k+4]));
            a[3] = f2tf(__uint_as_float(Qs[(rloc+8)*68 + k+4]));
            #pragma unroll
            for (int ni = 0; ni < 8; ++ni){
                int n = ni*8 + (lane>>2);
                unsigned bf[2] = { Ks[n*68 + k], Ks[n*68 + k+4] };
                mma8(c_[ni], a, bf);
            }
        }

        const int hb = b*NH + h;
        float mm0 = gm[(long)hb*S_LEN + q0 + rloc];
        float mm1 = gm[(long)hb*S_LEN + q0 + rloc + 8];
        float il0 = 1.f / gl[(long)hb*S_LEN + q0 + rloc];
        float il1 = 1.f / gl[(long)hb*S_LEN + q0 + rloc + 8];
        #pragma unroll
        for (int ni = 0; ni < 8; ++ni){
            acc[ni][0] += __expf(c_[ni][0]-mm0)*il0;
            acc[ni][1] += __expf(c_[ni][1]-mm0)*il0;
            acc[ni][2] += __expf(c_[ni][2]-mm1)*il1;
            acc[ni][3] += __expf(c_[ni][3]-mm1)*il1;
        }
        __syncthreads();
    }

    float* out = avg + (long)b*S2;
    const float s = 1.0f/NH;
    #pragma unroll
    for (int ni = 0; ni < 8; ++ni){
        int kc = k0 + ni*8 + 2*(lane&3);
        *(float2*)(out + (long)(q0+rloc)  *S_LEN + kc) = make_float2(acc[ni][0]*s, acc[ni][1]*s);
        *(float2*)(out + (long)(q0+rloc+8)*S_LEN + kc) = make_float2(acc[ni][2]*s, acc[ni][3]*s);
    }
}

// ---------------------------------------------------------------------------
extern "C" void kernel_launch(void* const* d_in, const int* in_sizes, int n_in,
                              void* d_out, int out_size)
{
    const float* query = (const float*)d_in[0];
    const float* key   = (const float*)d_in[1];
    const float* value = (const float*)d_in[2];
    const float* q_w = (const float*)d_in[3];
    const float* q_b = (const float*)d_in[4];
    const float* k_w = (const float*)d_in[5];
    const float* k_b = (const float*)d_in[6];
    const float* v_w = (const float*)d_in[7];
    const float* v_b = (const float*)d_in[8];
    const float* out_w = (const float*)d_in[9];
    const float* out_b = (const float*)d_in[10];

    float *qp, *kp, *vp, *op, *gm, *gl;
    cudaGetSymbolAddress((void**)&qp, g_Qp);
    cudaGetSymbolAddress((void**)&kp, g_Kp);
    cudaGetSymbolAddress((void**)&vp, g_Vp);
    cudaGetSymbolAddress((void**)&op, g_O);
    cudaGetSymbolAddress((void**)&gm, g_m);
    cudaGetSymbolAddress((void**)&gl, g_l);

    float* Z = (float*)d_out;                          // [S,B,E]
    float* attn_avg = (float*)d_out + (long)MROWS*EMB; // [B,S,S]

    // 1) Q/K/V projections merged
    dim3 gqkv(EMB/128, MROWS/64, 3);
    qkv_proj<<<gqkv, 256>>>(query, key, value, q_w, q_b, k_w, k_b, v_w, v_b, qp, kp, vp);

    // 2) Flash attention (round-5 config: 128 thr, q-tile 128)
    dim3 gfa(NHEADS, S_LEN/128, 1);
    flash_attn<<<gfa, 128>>>(qp, kp, vp, op, gm, gl);

    // 3) Output projection
    dim3 gop(EMB/128, MROWS/64, 1);
    out_proj<<<gop, 256>>>(op, out_w, out_b, Z);

    // 4) attn_avg v4 (round-6 config: 256 thr, double-buffered heads)
    cudaFuncSetAttribute(avg_attn, cudaFuncAttributeMaxDynamicSharedMemorySize, 104448);
    dim3 gav(S_LEN/64, S_LEN/128, BSZ);
    avg_attn<<<gav, 256, 104448>>>(qp, kp, gm, gl, attn_avg);
}

// round 8
// speedup vs baseline: 1.2072x; 1.0228x over previous
#include <cuda_runtime.h>

#define S_LEN 2048
#define BSZ   2
#define EMB   1024
#define NH    16
#define DH    64
#define MROWS 4096
#define NHEADS 32
#define S2 ((long)S_LEN*S_LEN)

// Scratch (__device__ globals per alloc-free rule)
__device__ float g_Qp[MROWS*EMB];   // column-permuted within 8-groups
__device__ float g_Kp[MROWS*EMB];   // column-permuted within 8-groups
__device__ float g_Vp[MROWS*EMB];   // normal layout
__device__ float g_O [MROWS*EMB];
__device__ float g_m [NHEADS*S_LEN];
__device__ float g_l [NHEADS*S_LEN];

__device__ __forceinline__ unsigned f2tf(float f){
    unsigned u; asm("cvt.rna.tf32.f32 %0, %1;" : "=r"(u) : "f"(f)); return u;
}
__device__ __forceinline__ void mma8(float* c, const unsigned* a, const unsigned* b){
    asm volatile("mma.sync.aligned.m16n8k8.row.col.f32.tf32.tf32.f32 "
      "{%0,%1,%2,%3}, {%4,%5,%6,%7}, {%8,%9}, {%0,%1,%2,%3};\n"
      : "+f"(c[0]), "+f"(c[1]), "+f"(c[2]), "+f"(c[3])
      : "r"(a[0]), "r"(a[1]), "r"(a[2]), "r"(a[3]), "r"(b[0]), "r"(b[1]));
}
__device__ __forceinline__ void cpa16(void* dst, const void* src){
    unsigned d = (unsigned)__cvta_generic_to_shared(dst);
    asm volatile("cp.async.cg.shared.global [%0], [%1], 16;\n" :: "r"(d), "l"(src));
}

// ---------------------------------------------------------------------------
// TN tf32 GEMM body. permOut: store C columns permuted within 8-groups
// (pairing (n, n+4) adjacently) for LDS.64 fragment consumers.
// ---------------------------------------------------------------------------
template<int BM,int BN,int BK,int WM,int WN,int NWARPS>
__device__ __forceinline__
void gemm_body(const float* __restrict__ A, int lda,
               const float* __restrict__ B, int ldb,
               float* __restrict__ C, int ldc,
               const float* __restrict__ bias, float scale, int K,
               int m0, int n0, bool permOut)
{
    constexpr int NT  = NWARPS*32;
    constexpr int LA  = BM*BK/(NT*4);
    constexpr int LB  = BN*BK/(NT*4);
    constexpr int WGN = BN/WN;
    constexpr int MI  = WM/16, NI = WN/8;
    constexpr int LDS_ = BK + 4;

    __shared__ unsigned As[2][BM][LDS_];
    __shared__ unsigned Bs[2][BN][LDS_];

    const int tid  = threadIdx.x;
    const int lane = tid & 31, wid = tid >> 5;
    const int wm = wid / WGN, wn = wid % WGN;

    float acc[MI][NI][4] = {};
    float4 ra[LA], rb[LB];

    auto ldtiles = [&](int k0){
        #pragma unroll
        for (int i = 0; i < LA; ++i){
            int idx = tid + i*NT;
            int r = idx / (BK/4), c = (idx % (BK/4)) * 4;
            ra[i] = *(const float4*)(A + (long)(m0+r)*lda + k0 + c);
        }
        #pragma unroll
        for (int i = 0; i < LB; ++i){
            int idx = tid + i*NT;
            int r = idx / (BK/4), c = (idx % (BK/4)) * 4;
            rb[i] = *(const float4*)(B + (long)(n0+r)*ldb + k0 + c);
        }
    };
    auto sttiles = [&](int buf){
        #pragma unroll
        for (int i = 0; i < LA; ++i){
            int idx = tid + i*NT;
            int r = idx / (BK/4), c = (idx % (BK/4)) * 4;
            uint4 u = { f2tf(ra[i].x), f2tf(ra[i].y), f2tf(ra[i].z), f2tf(ra[i].w) };
            *(uint4*)&As[buf][r][c] = u;
        }
        #pragma unroll
        for (int i = 0; i < LB; ++i){
            int idx = tid + i*NT;
            int r = idx / (BK/4), c = (idx % (BK/4)) * 4;
            uint4 u = { f2tf(rb[i].x), f2tf(rb[i].y), f2tf(rb[i].z), f2tf(rb[i].w) };
            *(uint4*)&Bs[buf][r][c] = u;
        }
    };
    auto compute = [&](int buf){
        #pragma unroll
        for (int ks = 0; ks < BK/8; ++ks){
            unsigned af[MI][4], bf[NI][2];
            #pragma unroll
            for (int mi = 0; mi < MI; ++mi){
                int m = wm*WM + mi*16 + (lane>>2);
                int k = ks*8 + (lane&3);
                af[mi][0] = As[buf][m  ][k  ];
                af[mi][1] = As[buf][m+8][k  ];
                af[mi][2] = As[buf][m  ][k+4];
                af[mi][3] = As[buf][m+8][k+4];
            }
            #pragma unroll
            for (int ni = 0; ni < NI; ++ni){
                int n = wn*WN + ni*8 + (lane>>2);
                int k = ks*8 + (lane&3);
                bf[ni][0] = Bs[buf][n][k  ];
                bf[ni][1] = Bs[buf][n][k+4];
            }
            #pragma unroll
            for (int mi = 0; mi < MI; ++mi)
                #pragma unroll
                for (int ni = 0; ni < NI; ++ni)
                    mma8(acc[mi][ni], af[mi], bf[ni]);
        }
    };

    ldtiles(0); sttiles(0); __syncthreads();
    const int nk = K/BK;
    for (int t = 1; t < nk; ++t){
        ldtiles(t*BK);
        compute((t-1)&1);
        sttiles(t&1);
        __syncthreads();
    }
    compute((nk-1)&1);

    #pragma unroll
    for (int mi = 0; mi < MI; ++mi){
        #pragma unroll
        for (int ni = 0; ni < NI; ++ni){
            int m = m0 + wm*WM + mi*16 + (lane>>2);
            int n = n0 + wn*WN + ni*8 + 2*(lane&3);
            float v0 = acc[mi][ni][0], v1 = acc[mi][ni][1];
            float v2 = acc[mi][ni][2], v3 = acc[mi][ni][3];
            float b0 = bias[n], b1 = bias[n+1];
            v0 = (v0+b0)*scale; v1 = (v1+b1)*scale;
            v2 = (v2+b0)*scale; v3 = (v3+b1)*scale;
            if (permOut){
                int p0 = (n & ~7) | ((n&3)<<1) | ((n>>2)&1);   // perm(n); perm(n+1)=p0+2
                C[(long)m    *ldc + p0    ] = v0;
                C[(long)m    *ldc + p0 + 2] = v1;
                C[(long)(m+8)*ldc + p0    ] = v2;
                C[(long)(m+8)*ldc + p0 + 2] = v3;
            } else {
                *(float2*)(C + (long)m    *ldc + n) = make_float2(v0, v1);
                *(float2*)(C + (long)(m+8)*ldc + n) = make_float2(v2, v3);
            }
        }
    }
}

// Merged Q/K/V projections: grid (8, 64, 3). Q,K written column-permuted.
__global__ __launch_bounds__(256)
void qkv_proj(const float* __restrict__ q, const float* __restrict__ k, const float* __restrict__ v,
              const float* __restrict__ qw, const float* __restrict__ qb,
              const float* __restrict__ kw, const float* __restrict__ kb,
              const float* __restrict__ vw, const float* __restrict__ vb,
              float* __restrict__ qp, float* __restrict__ kp, float* __restrict__ vp)
{
    const int z = blockIdx.z;
    const float* A  = (z==0)? q  : (z==1)? k  : v;
    const float* W  = (z==0)? qw : (z==1)? kw : vw;
    const float* bi = (z==0)? qb : (z==1)? kb : vb;
    float*       C  = (z==0)? qp : (z==1)? kp : vp;
    const float scale = (z==0)? 0.125f : 1.0f;
    gemm_body<64,128,16,32,32,8>(A, EMB, W, EMB, C, EMB, bi, scale, EMB,
                                 blockIdx.y*64, blockIdx.x*128, z<2);
}

// Output projection: grid (8, 64)
__global__ __launch_bounds__(256)
void out_proj(const float* __restrict__ A, const float* __restrict__ W,
              const float* __restrict__ bi, float* __restrict__ C)
{
    gemm_body<64,128,16,32,32,8>(A, EMB, W, EMB, C, EMB, bi, 1.0f, EMB,
                                 blockIdx.y*64, blockIdx.x*128, false);
}

// ---------------------------------------------------------------------------
// Flash attention: q-tile 128, 4 warps (MI=2), k-tiles 32 double-buffered.
// Q/K in permuted layout -> fragment loads are LDS.64 (stride 72, conflict-free).
// ---------------------------------------------------------------------------
__global__ __launch_bounds__(128)
void flash_attn(const float* __restrict__ qp, const float* __restrict__ kp,
                const float* __restrict__ vp, float* __restrict__ op,
                float* __restrict__ gm, float* __restrict__ gl)
{
    __shared__ __align__(16) unsigned SU[9216];
    const int tid = threadIdx.x, lane = tid&31, w = tid>>5;
    const int hb = blockIdx.x, h = hb&15, b = hb>>4;
    const int q0 = blockIdx.y*128;
    const long base = (long)b*EMB + h*DH;
    const float* Qg = qp + base + (long)q0*(BSZ*EMB);
    const float* Kg = kp + base;
    const float* Vg = vp + base;

    // stage Q (permuted layout, raw bits), build RNA tf32 A-fragments
    for (int i = tid; i < 2048; i += 128){
        int r = i>>4, c = (i&15)*4;
        cpa16(&SU[r*72 + c], Qg + (long)r*(BSZ*EMB) + c);
    }
    asm volatile("cp.async.commit_group;\n");
    asm volatile("cp.async.wait_group 0;\n");
    __syncthreads();

    unsigned Qa[8][2][4];
    {
        const int p = lane>>2, col0 = 2*(lane&3);
        #pragma unroll
        for (int ks = 0; ks < 8; ++ks)
            #pragma unroll
            for (int mi = 0; mi < 2; ++mi){
                int m = w*32 + mi*16 + p;
                int col = ks*8 + col0;
                uint2 u0 = *(const uint2*)&SU[ m   *72 + col];
                uint2 u1 = *(const uint2*)&SU[(m+8)*72 + col];
                Qa[ks][mi][0] = f2tf(__uint_as_float(u0.x));
                Qa[ks][mi][1] = f2tf(__uint_as_float(u1.x));
                Qa[ks][mi][2] = f2tf(__uint_as_float(u0.y));
                Qa[ks][mi][3] = f2tf(__uint_as_float(u1.y));
            }
    }
    __syncthreads();

    unsigned* const Kb0 = SU;
    unsigned* const Kb1 = SU + 2304;     // 32*72
    unsigned* const Vb0 = SU + 4608;
    unsigned* const Vb1 = SU + 6912;

    auto load_kv = [&](int kt, int sel){
        unsigned* Kb = sel ? Kb1 : Kb0;
        unsigned* Vb = sel ? Vb1 : Vb0;
        const long r0 = (long)kt*32;
        #pragma unroll
        for (int j = 0; j < 4; ++j){
            int cch = tid + j*128;
            int r = cch>>4, cc = (cch&15)*4;
            cpa16(&Kb[r*72 + cc], Kg + (r0+r)*(BSZ*EMB) + cc);
            cpa16(&Vb[r*72 + cc], Vg + (r0+r)*(BSZ*EMB) + cc);
        }
    };

    float m_[2][2] = {{-1e30f,-1e30f},{-1e30f,-1e30f}};
    float l_[2][2] = {};
    float o[2][8][4] = {};

    const int srcA = (lane & ~3) | ((lane&3)>>1);
    const int srcB = srcA + 2;
    const bool osel = (lane & 1);

    load_kv(0, 0);
    asm volatile("cp.async.commit_group;\n");

    for (int t = 0; t < 64; ++t){
        if (t < 63){
            load_kv(t+1, (t+1)&1);
            asm volatile("cp.async.commit_group;\n");
            asm volatile("cp.async.wait_group 1;\n");
        } else {
            asm volatile("cp.async.wait_group 0;\n");
        }
        __syncthreads();

        unsigned* Kb = (t&1) ? Kb1 : Kb0;
        unsigned* Vb = (t&1) ? Vb1 : Vb0;

        // S = Q K^T  (K fragments via LDS.64)
        float c_[2][4][4] = {};
        #pragma unroll
        for (int ks = 0; ks < 8; ++ks){
            unsigned bf[4][2];
            #pragma unroll
            for (int ni = 0; ni < 4; ++ni){
                int n = ni*8 + (lane>>2);
                int col = ks*8 + 2*(lane&3);
                uint2 u = *(const uint2*)&Kb[n*72 + col];
                bf[ni][0] = u.x; bf[ni][1] = u.y;
            }
            #pragma unroll
            for (int mi = 0; mi < 2; ++mi)
                #pragma unroll
                for (int ni = 0; ni < 4; ++ni)
                    mma8(c_[mi][ni], Qa[ks][mi], bf[ni]);
        }

        // online softmax with rescale-skip
        #pragma unroll
        for (int mi = 0; mi < 2; ++mi){
            float mx0 = -1e30f, mx1 = -1e30f;
            #pragma unroll
            for (int ni = 0; ni < 4; ++ni){
                mx0 = fmaxf(mx0, fmaxf(c_[mi][ni][0], c_[mi][ni][1]));
                mx1 = fmaxf(mx1, fmaxf(c_[mi][ni][2], c_[mi][ni][3]));
            }
            mx0 = fmaxf(mx0, __shfl_xor_sync(0xffffffffu, mx0, 1));
            mx0 = fmaxf(mx0, __shfl_xor_sync(0xffffffffu, mx0, 2));
            mx1 = fmaxf(mx1, __shfl_xor_sync(0xffffffffu, mx1, 1));
            mx1 = fmaxf(mx1, __shfl_xor_sync(0xffffffffu, mx1, 2));
            float mn0 = fmaxf(m_[mi][0], mx0), mn1 = fmaxf(m_[mi][1], mx1);
            if (!__all_sync(0xffffffffu, (mn0 == m_[mi][0]) & (mn1 == m_[mi][1]))){
                float f0 = __expf(m_[mi][0] - mn0), f1 = __expf(m_[mi][1] - mn1);
                l_[mi][0] *= f0; l_[mi][1] *= f1;
                #pragma unroll
                for (int ni = 0; ni < 8; ++ni){
                    o[mi][ni][0]*=f0; o[mi][ni][1]*=f0;
                    o[mi][ni][2]*=f1; o[mi][ni][3]*=f1;
                }
                m_[mi][0] = mn0; m_[mi][1] = mn1;
            }
            float s0 = 0.f, s1 = 0.f;
            #pragma unroll
            for (int ni = 0; ni < 4; ++ni){
                c_[mi][ni][0] = __expf(c_[mi][ni][0]-m_[mi][0]);
                c_[mi][ni][1] = __expf(c_[mi][ni][1]-m_[mi][0]);
                c_[mi][ni][2] = __expf(c_[mi][ni][2]-m_[mi][1]);
                c_[mi][ni][3] = __expf(c_[mi][ni][3]-m_[mi][1]);
                s0 += c_[mi][ni][0]+c_[mi][ni][1];
                s1 += c_[mi][ni][2]+c_[mi][ni][3];
            }
            s0 += __shfl_xor_sync(0xffffffffu, s0, 1);
            s0 += __shfl_xor_sync(0xffffffffu, s0, 2);
            s1 += __shfl_xor_sync(0xffffffffu, s1, 1);
            s1 += __shfl_xor_sync(0xffffffffu, s1, 2);
            l_[mi][0] += s0; l_[mi][1] += s1;
        }

        // P @ V
        #pragma unroll
        for (int ks2 = 0; ks2 < 4; ++ks2){
            unsigned a[2][4];
            #pragma unroll
            for (int mi = 0; mi < 2; ++mi){
                float v00 = __shfl_sync(0xffffffffu, c_[mi][ks2][0], srcA);
                float v01 = __shfl_sync(0xffffffffu, c_[mi][ks2][1], srcA);
                float v10 = __shfl_sync(0xffffffffu, c_[mi][ks2][2], srcA);
                float v11 = __shfl_sync(0xffffffffu, c_[mi][ks2][3], srcA);
                float v40 = __shfl_sync(0xffffffffu, c_[mi][ks2][0], srcB);
                float v41 = __shfl_sync(0xffffffffu, c_[mi][ks2][1], srcB);
                float v50 = __shfl_sync(0xffffffffu, c_[mi][ks2][2], srcB);
                float v51 = __shfl_sync(0xffffffffu, c_[mi][ks2][3], srcB);
                a[mi][0] = f2tf(osel ? v01 : v00);
                a[mi][1] = f2tf(osel ? v11 : v10);
                a[mi][2] = f2tf(osel ? v41 : v40);
                a[mi][3] = f2tf(osel ? v51 : v50);
            }
            #pragma unroll
            for (int ni = 0; ni < 8; ++ni){
                int kk = ks2*8 + (lane&3);
                int n  = ni*8 + (lane>>2);
                unsigned bf[2] = { Vb[kk*72 + n], Vb[(kk+4)*72 + n] };
                mma8(o[0][ni], a[0], bf);
                mma8(o[1][ni], a[1], bf);
            }
        }
        __syncthreads();
    }

    float* Og = op + base + (long)q0*(BSZ*EMB);
    #pragma unroll
    for (int mi = 0; mi < 2; ++mi){
        float inv0 = 1.f/l_[mi][0], inv1 = 1.f/l_[mi][1];
        int m = w*32 + mi*16 + (lane>>2);
        #pragma unroll
        for (int ni = 0; ni < 8; ++ni){
            int d = ni*8 + 2*(lane&3);
            *(float2*)(Og + (long)m    *(BSZ*EMB) + d) = make_float2(o[mi][ni][0]*inv0, o[mi][ni][1]*inv0);
            *(float2*)(Og + (long)(m+8)*(BSZ*EMB) + d) = make_float2(o[mi][ni][2]*inv1, o[mi][ni][3]*inv1);
        }
        if ((lane & 3) == 0){
            gm[(long)hb*S_LEN + q0 + m]     = m_[mi][0];
            gm[(long)hb*S_LEN + q0 + m + 8] = m_[mi][1];
            gl[(long)hb*S_LEN + q0 + m]     = l_[mi][0];
            gl[(long)hb*S_LEN + q0 + m + 8] = l_[mi][1];
        }
    }
}

// ---------------------------------------------------------------------------
// attn_avg: 256-thread blocks, k-tile 64, q-tile 128, double-buffered heads.
// Q/K permuted layout -> all fragment loads LDS.64 (stride 72, conflict-free).
// Dynamic smem: 2 x (128*72 + 64*72) x 4 = 110592 B.
// ---------------------------------------------------------------------------
__global__ __launch_bounds__(256)
void avg_attn(const float* __restrict__ qp, const float* __restrict__ kp,
              const float* __restrict__ gm, const float* __restrict__ gl,
              float* __restrict__ avg)
{
    extern __shared__ __align__(16) unsigned ASH[];
    constexpr int BUF = 128*72 + 64*72;   // 13824 words
    const int tid = threadIdx.x, lane = tid&31, wid = tid>>5;
    const int k0 = blockIdx.x*64, q0 = blockIdx.y*128, b = blockIdx.z;
    const int rloc = wid*16 + (lane>>2);

    auto stage = [&](int h, int sel){
        unsigned* Qs = ASH + sel*BUF;
        unsigned* Ks = Qs + 128*72;
        const long base = (long)b*EMB + h*DH;
        #pragma unroll
        for (int j = 0; j < 8; ++j){
            int idx = tid + j*256;
            int r = idx>>4, c = (idx&15)*4;
            cpa16(&Qs[r*72 + c], qp + base + (long)(q0+r)*(BSZ*EMB) + c);
        }
        #pragma unroll
        for (int j = 0; j < 4; ++j){
            int idx = tid + j*256;
            int r = idx>>4, c = (idx&15)*4;
            cpa16(&Ks[r*72 + c], kp + base + (long)(k0+r)*(BSZ*EMB) + c);
        }
        asm volatile("cp.async.commit_group;\n");
    };

    float acc[8][4] = {};

    stage(0, 0);
    for (int h = 0; h < NH; ++h){
        if (h < NH-1){
            stage(h+1, (h+1)&1);
            asm volatile("cp.async.wait_group 1;\n");
        } else {
            asm volatile("cp.async.wait_group 0;\n");
        }
        __syncthreads();

        unsigned* Qs = ASH + (h&1)*BUF;
        unsigned* Ks = Qs + 128*72;

        float c_[8][4] = {};
        #pragma unroll
        for (int ks = 0; ks < 8; ++ks){
            int col = ks*8 + 2*(lane&3);
            uint2 u0 = *(const uint2*)&Qs[ rloc   *72 + col];
            uint2 u1 = *(const uint2*)&Qs[(rloc+8)*72 + col];
            unsigned a[4] = { f2tf(__uint_as_float(u0.x)), f2tf(__uint_as_float(u1.x)),
                              f2tf(__uint_as_float(u0.y)), f2tf(__uint_as_float(u1.y)) };
            #pragma unroll
            for (int ni = 0; ni < 8; ++ni){
                int n = ni*8 + (lane>>2);
                uint2 ub = *(const uint2*)&Ks[n*72 + col];
                unsigned bf[2] = { ub.x, ub.y };
                mma8(c_[ni], a, bf);
            }
        }

        const int hb = b*NH + h;
        float mm0 = gm[(long)hb*S_LEN + q0 + rloc];
        float mm1 = gm[(long)hb*S_LEN + q0 + rloc + 8];
        float il0 = 1.f / gl[(long)hb*S_LEN + q0 + rloc];
        float il1 = 1.f / gl[(long)hb*S_LEN + q0 + rloc + 8];
        #pragma unroll
        for (int ni = 0; ni < 8; ++ni){
            acc[ni][0] += __expf(c_[ni][0]-mm0)*il0;
            acc[ni][1] += __expf(c_[ni][1]-mm0)*il0;
            acc[ni][2] += __expf(c_[ni][2]-mm1)*il1;
            acc[ni][3] += __expf(c_[ni][3]-mm1)*il1;
        }
        __syncthreads();
    }

    float* out = avg + (long)b*S2;
    const float s = 1.0f/NH;
    #pragma unroll
    for (int ni = 0; ni < 8; ++ni){
        int kc = k0 + ni*8 + 2*(lane&3);
        *(float2*)(out + (long)(q0+rloc)  *S_LEN + kc) = make_float2(acc[ni][0]*s, acc[ni][1]*s);
        *(float2*)(out + (long)(q0+rloc+8)*S_LEN + kc) = make_float2(acc[ni][2]*s, acc[ni][3]*s);
    }
}

// ---------------------------------------------------------------------------
extern "C" void kernel_launch(void* const* d_in, const int* in_sizes, int n_in,
                              void* d_out, int out_size)
{
    const float* query = (const float*)d_in[0];
    const float* key   = (const float*)d_in[1];
    const float* value = (const float*)d_in[2];
    const float* q_w = (const float*)d_in[3];
    const float* q_b = (const float*)d_in[4];
    const float* k_w = (const float*)d_in[5];
    const float* k_b = (const float*)d_in[6];
    const float* v_w = (const float*)d_in[7];
    const float* v_b = (const float*)d_in[8];
    const float* out_w = (const float*)d_in[9];
    const float* out_b = (const float*)d_in[10];

    float *qp, *kp, *vp, *op, *gm, *gl;
    cudaGetSymbolAddress((void**)&qp, g_Qp);
    cudaGetSymbolAddress((void**)&kp, g_Kp);
    cudaGetSymbolAddress((void**)&vp, g_Vp);
    cudaGetSymbolAddress((void**)&op, g_O);
    cudaGetSymbolAddress((void**)&gm, g_m);
    cudaGetSymbolAddress((void**)&gl, g_l);

    float* Z = (float*)d_out;                          // [S,B,E]
    float* attn_avg = (float*)d_out + (long)MROWS*EMB; // [B,S,S]

    // one-time stream/event setup (first call = eager correctness run)
    static cudaStream_t s2 = nullptr;
    static cudaEvent_t evFork = nullptr, evJoin = nullptr;
    if (!s2){
        cudaStreamCreateWithFlags(&s2, cudaStreamNonBlocking);
        cudaEventCreateWithFlags(&evFork, cudaEventDisableTiming);
        cudaEventCreateWithFlags(&evJoin, cudaEventDisableTiming);
        cudaFuncSetAttribute(avg_attn, cudaFuncAttributeMaxDynamicSharedMemorySize, 110592);
    }

    // 1) Q/K/V projections merged (Q,K column-permuted for LDS.64 consumers)
    dim3 gqkv(EMB/128, MROWS/64, 3);
    qkv_proj<<<gqkv, 256>>>(query, key, value, q_w, q_b, k_w, k_b, v_w, v_b, qp, kp, vp);

    // 2) Flash attention
    dim3 gfa(NHEADS, S_LEN/128, 1);
    flash_attn<<<gfa, 128>>>(qp, kp, vp, op, gm, gl);

    // fork: out_proj on s2 concurrent with avg_attn on main stream
    cudaEventRecord(evFork, 0);
    cudaStreamWaitEvent(s2, evFork, 0);

    dim3 gop(EMB/128, MROWS/64, 1);
    out_proj<<<gop, 256, 0, s2>>>(op, out_w, out_b, Z);
    cudaEventRecord(evJoin, s2);

    dim3 gav(S_LEN/64, S_LEN/128, BSZ);
    avg_attn<<<gav, 256, 110592>>>(qp, kp, gm, gl, attn_avg);

    // join
    cudaStreamWaitEvent(0, evJoin, 0);
}